// round 5
// baseline (speedup 1.0000x reference)
#include <cuda_runtime.h>

// Problem constants
#define N_B    64
#define T_T    2048
#define IN_P   8
#define C_C    2
#define M_M    10
#define NSTEP  2047            // number of increments (T-1)
#define LSEG   8               // steps per segment
#define SSEG   256             // segments per chain
#define NCHAIN 128             // N*C
#define NU1    (NCHAIN * SSEG) // 32768 segment units
#define GRP    16
#define NU2    (NCHAIN * (SSEG / GRP)) // 2048
#define NU3    NCHAIN                  // 128

// Scratch (static device arrays; allocation-free)
__device__ float g_part1[NU1 * 100]; // [unit][col][row], col-major per matrix
__device__ float g_part2[NU2 * 100];

// Distributed 10x10 matmul: acc = Cm @ Gm
// 5 lanes per matrix; lane owns columns {2q, 2q+1} of every matrix.
// Cm (left) columns come from lanes of the group via shuffle; Gm (right) local.
__device__ __forceinline__ void mm10(const float Cm[2][10], const float Gm[2][10],
                                     int g5, float acc[2][10])
{
#pragma unroll
    for (int j = 0; j < 2; ++j)
#pragma unroll
        for (int r = 0; r < 10; ++r) acc[j][r] = 0.f;
#pragma unroll
    for (int m = 0; m < 10; ++m) {
        int src = g5 + (m >> 1);
        float cv[10];
#pragma unroll
        for (int r = 0; r < 10; ++r)
            cv[r] = __shfl_sync(0xFFFFFFFFu, Cm[m & 1][r], src);
#pragma unroll
        for (int j = 0; j < 2; ++j) {
            float gv = Gm[j][m];
#pragma unroll
            for (int r = 0; r < 10; ++r)
                acc[j][r] = fmaf(cv[r], gv, acc[j][r]);
        }
    }
}

// Kernel 1: per-(chain,segment) ordered product of expm(G_t) over LSEG steps.
// exp(G) via Paterson-Stockmeyer Horner-in-G^2, Taylor degree 9:
//   E = B0 + G2*(B1 + G2*(B2 + G2*(B3 + G2*B4))),  Bi = I/(2i)! + G/(2i+1)!
// Then P <- P @ E.  6 matmuls/step (vs 10 for plain Horner).
__global__ void __launch_bounds__(256, 2)
seg_kernel(const float* __restrict__ x, const float* __restrict__ A)
{
    // skew in shared, layout [i][m][c][j]: lane reads within 20 consecutive floats
    __shared__ float sk[IN_P * M_M * C_C * M_M]; // 1600 floats
    for (int idx = threadIdx.x; idx < C_C * IN_P * M_M * M_M; idx += blockDim.x) {
        int j = idx % M_M;
        int m = (idx / M_M) % M_M;
        int i = (idx / (M_M * M_M)) % IN_P;
        int c = idx / (M_M * M_M * IN_P);
        float v = A[((c * IN_P + i) * M_M + m) * M_M + j]
                - A[((c * IN_P + i) * M_M + j) * M_M + m];
        sk[((i * M_M + m) * C_C + c) * M_M + j] = v;
    }
    __syncthreads();

    int lane = threadIdx.x & 31;
    int warp = (blockIdx.x * blockDim.x + threadIdx.x) >> 5;
    int g = lane / 5; if (g > 5) g = 5;      // lanes 30,31 shadow group 5
    int q = lane - g * 5; if (q > 4) q = 4;  // duplicate cols 8,9 (never stored)
    int g5 = g * 5;
    int unitRaw = warp * 6 + g;
    int unit = (unitRaw < NU1) ? unitRaw : (NU1 - 1);
    bool active = (lane < 30) && (unitRaw < NU1);
    int chain = unit / SSEG;
    int seg   = unit % SSEG;
    int n = chain >> 1;
    int c = chain & 1;
    int j0 = q * 2;

    const float4* X4 = (const float4*)x;
    int t0 = seg * LSEG;
    int rb = (n * T_T + t0) * 2;
    float4 xa = X4[rb], xb = X4[rb + 1];

    float P[2][10];
#pragma unroll
    for (int j = 0; j < 2; ++j)
#pragma unroll
        for (int r = 0; r < 10; ++r) P[j][r] = (r == j0 + j) ? 1.f : 0.f;

    // Taylor reciprocal factorials 1/k!, k=0..9
    const float a0 = 1.f, a1 = 1.f, a2 = 0.5f, a3 = 1.f/6.f, a4 = 1.f/24.f,
                a5 = 1.f/120.f, a6 = 1.f/720.f, a7 = 1.f/5040.f,
                a8 = 1.f/40320.f, a9 = 1.f/362880.f;

#pragma unroll 1
    for (int s = 0; s < LSEG; ++s) {
        int t = t0 + s;
        int tn = (t < NSTEP) ? (t + 1) : t; // tail: tn==t -> dx=0 -> E=I
        int rn = (n * T_T + tn) * 2;
        float4 ya = X4[rn], yb = X4[rn + 1];
        float dx[8];
        dx[0] = ya.x - xa.x; dx[1] = ya.y - xa.y; dx[2] = ya.z - xa.z; dx[3] = ya.w - xa.w;
        dx[4] = yb.x - xb.x; dx[5] = yb.y - xb.y; dx[6] = yb.z - xb.z; dx[7] = yb.w - xb.w;
        xa = ya; xb = yb;

        // G columns: G[m][j0+j] = sum_i dx[i]*skew[c][i][m][j0+j]
        float G[2][10];
#pragma unroll
        for (int j = 0; j < 2; ++j) {
#pragma unroll
            for (int m = 0; m < 10; ++m) G[j][m] = 0.f;
#pragma unroll
            for (int i = 0; i < 8; ++i) {
                float d = dx[i];
#pragma unroll
                for (int m = 0; m < 10; ++m)
                    G[j][m] = fmaf(d, sk[((i * M_M + m) * C_C + c) * M_M + j0 + j], G[j][m]);
            }
        }

        // G2 = G @ G
        float G2[2][10];
        mm10(G, G, g5, G2);

        // W = B4 = a8*I + a9*G
        float W[2][10];
#pragma unroll
        for (int j = 0; j < 2; ++j)
#pragma unroll
            for (int r = 0; r < 10; ++r)
                W[j][r] = fmaf(a9, G[j][r], (r == j0 + j) ? a8 : 0.f);

        // Horner in G2:  W = G2 @ W + Bi,  i = 3,2,1,0
#pragma unroll
        for (int i = 3; i >= 0; --i) {
            float ai = (i == 3) ? a6 : (i == 2) ? a4 : (i == 1) ? a2 : a0;
            float bi = (i == 3) ? a7 : (i == 2) ? a5 : (i == 1) ? a3 : a1;
            float acc[2][10];
            mm10(G2, W, g5, acc);
#pragma unroll
            for (int j = 0; j < 2; ++j)
#pragma unroll
                for (int r = 0; r < 10; ++r)
                    W[j][r] = fmaf(bi, G[j][r], acc[j][r]) + ((r == j0 + j) ? ai : 0.f);
        }

        // P <- P @ E
        float acc[2][10];
        mm10(P, W, g5, acc);
#pragma unroll
        for (int j = 0; j < 2; ++j)
#pragma unroll
            for (int r = 0; r < 10; ++r) P[j][r] = acc[j][r];
    }

    if (active) {
        float* dst = g_part1 + unit * 100 + j0 * 10;
#pragma unroll
        for (int j = 0; j < 2; ++j)
#pragma unroll
            for (int r = 0; r < 10; ++r) dst[j * 10 + r] = P[j][r];
    }
}

// Combine kernel: ordered product of GRP consecutive partials.
// mode 0: g_part1 -> g_part2 ; mode 1: g_part2 -> out (row-major store)
// Loads are software-pipelined (prefetch next E during current matmul).
__global__ void __launch_bounds__(256)
comb_kernel(int nUnits, int mode, float* __restrict__ out)
{
    const float* src = (mode == 0) ? g_part1 : g_part2;
    int lane = threadIdx.x & 31;
    int warp = (blockIdx.x * blockDim.x + threadIdx.x) >> 5;
    int g = lane / 5; if (g > 5) g = 5;
    int q = lane - g * 5; if (q > 4) q = 4;
    int g5 = g * 5;
    int unitRaw = warp * 6 + g;
    int unit = (unitRaw < nUnits) ? unitRaw : (nUnits - 1);
    bool active = (lane < 30) && (unitRaw < nUnits);
    int j0 = q * 2;

    const float* base = src + unit * (GRP * 100);
    float P[2][10];
#pragma unroll
    for (int j = 0; j < 2; ++j)
#pragma unroll
        for (int r = 0; r < 10; ++r)
            P[j][r] = base[(j0 + j) * 10 + r];

    float En[2][10];
#pragma unroll
    for (int j = 0; j < 2; ++j)
#pragma unroll
        for (int r = 0; r < 10; ++r)
            En[j][r] = base[100 + (j0 + j) * 10 + r];

#pragma unroll 1
    for (int e = 1; e < GRP; ++e) {
        float E[2][10];
#pragma unroll
        for (int j = 0; j < 2; ++j)
#pragma unroll
            for (int r = 0; r < 10; ++r) E[j][r] = En[j][r];
        if (e + 1 < GRP) {
            const float* nb = base + (e + 1) * 100;
#pragma unroll
            for (int j = 0; j < 2; ++j)
#pragma unroll
                for (int r = 0; r < 10; ++r)
                    En[j][r] = nb[(j0 + j) * 10 + r];
        }
        float acc[2][10];
        mm10(P, E, g5, acc);
#pragma unroll
        for (int j = 0; j < 2; ++j)
#pragma unroll
            for (int r = 0; r < 10; ++r) P[j][r] = acc[j][r];
    }

    if (active) {
        if (mode == 0) {
            float* dst = g_part2 + unit * 100 + j0 * 10;
#pragma unroll
            for (int j = 0; j < 2; ++j)
#pragma unroll
                for (int r = 0; r < 10; ++r) dst[j * 10 + r] = P[j][r];
        } else {
            float* dst = out + unit * 100; // unit == chain = n*C + c
#pragma unroll
            for (int j = 0; j < 2; ++j)
#pragma unroll
                for (int r = 0; r < 10; ++r) dst[r * 10 + (j0 + j)] = P[j][r];
        }
    }
}

extern "C" void kernel_launch(void* const* d_in, const int* in_sizes, int n_in,
                              void* d_out, int out_size)
{
    const float* x = (const float*)d_in[0];
    const float* A = (const float*)d_in[1];
    if (n_in >= 2 && in_sizes[0] == C_C * IN_P * M_M * M_M) { // defensive order check
        x = (const float*)d_in[1];
        A = (const float*)d_in[0];
    }
    float* out = (float*)d_out;

    int b1 = (NU1 + 47) / 48;
    seg_kernel<<<b1, 256>>>(x, A);
    int b2 = (NU2 + 47) / 48;
    comb_kernel<<<b2, 256>>>(NU2, 0, out);
    int b3 = (NU3 + 47) / 48;
    comb_kernel<<<b3, 256>>>(NU3, 1, out);
}

// round 7
// speedup vs baseline: 1.6834x; 1.6834x over previous
#include <cuda_runtime.h>

// Problem constants
#define N_B    64
#define T_T    2048
#define IN_P   8
#define C_C    2
#define M_M    10
#define NSTEP  2047            // number of increments (T-1)
#define LSEG   8               // steps per segment
#define SSEG   256             // segments per chain
#define NCHAIN 128             // N*C
#define NU1    (NCHAIN * SSEG) // 32768 segment units
#define GRP    16
#define NU2    (NCHAIN * (SSEG / GRP)) // 2048
#define NU3    NCHAIN                  // 128

#define CS 12                  // smem column stride (floats), 48B -> LDS.128-aligned
#define MS 132                 // smem matrix stride; 132 % 32 == 4 -> conflict-free across 6 groups
#define WS (6 * MS)            // per-warp smem stride (792 floats)

// Scratch (static device arrays; allocation-free)
__device__ float g_part1[NU1 * 100]; // [unit][col][row], col-major per matrix
__device__ float g_part2[NU2 * 100];

// acc = S @ W : S is 10x10 col-major (stride CS) in shared; W = lane's 2 columns.
// All 5 lanes of a group read the same address -> broadcast; across groups the
// 4g+12m bank pattern is disjoint -> conflict-free. 30 LDS insts per matmul.
__device__ __forceinline__ void mm10s(const float* __restrict__ S,
                                      const float W[2][10], float acc[2][10])
{
#pragma unroll
    for (int j = 0; j < 2; ++j)
#pragma unroll
        for (int r = 0; r < 10; ++r) acc[j][r] = 0.f;
#pragma unroll
    for (int m = 0; m < 10; ++m) {
        const float* col = S + m * CS;
        float4 v0 = *(const float4*)(col);
        float4 v1 = *(const float4*)(col + 4);
        float2 v2 = *(const float2*)(col + 8);
        float cv[10] = {v0.x, v0.y, v0.z, v0.w, v1.x, v1.y, v1.z, v1.w, v2.x, v2.y};
        float w0 = W[0][m], w1 = W[1][m];
#pragma unroll
        for (int r = 0; r < 10; ++r) acc[0][r] = fmaf(cv[r], w0, acc[0][r]);
#pragma unroll
        for (int r = 0; r < 10; ++r) acc[1][r] = fmaf(cv[r], w1, acc[1][r]);
    }
}

// Store lane's 2 columns into the group's smem tile (6 STS insts).
__device__ __forceinline__ void store_cols(float* __restrict__ S,
                                           const float V[2][10], int j0)
{
#pragma unroll
    for (int j = 0; j < 2; ++j) {
        float* p = S + (j0 + j) * CS;
        *(float4*)(p)     = make_float4(V[j][0], V[j][1], V[j][2], V[j][3]);
        *(float4*)(p + 4) = make_float4(V[j][4], V[j][5], V[j][6], V[j][7]);
        *(float2*)(p + 8) = make_float2(V[j][8], V[j][9]);
    }
}

// Kernel 1: per-(chain,segment) ordered product of expm(G_t) over LSEG steps.
// exp(G) via Paterson-Stockmeyer Horner-in-G^2, Taylor degree 7:
//   E = B0 + G2*(B1 + G2*(B2 + G2*B3)),  Bi = I/(2i)! + G/(2i+1)!
// Then P <- P @ E.  5 matmuls/step; G2 lives only in shared memory.
__global__ void __launch_bounds__(256, 2)
seg_kernel(const float* __restrict__ x, const float* __restrict__ A)
{
    // skew repacked: skp[((c*8+i)*5+q)*20 + m*2 + jj] = skew[c][i][m][2q+jj]
    // -> a lane's G-gen reads are 5x LDS.128 per i (vectorized, conflict-free).
    __shared__ __align__(16) float skp[1600];
    __shared__ __align__(16) float smat[8 * WS];

    for (int idx = threadIdx.x; idx < 1600; idx += 256) {
        int jj = idx & 1;
        int m  = (idx >> 1) % 10;
        int qq = (idx / 20) % 5;
        int i  = (idx / 100) % 8;
        int c  = idx / 800;
        int col = 2 * qq + jj;
        skp[idx] = A[((c * 8 + i) * 10 + m) * 10 + col]
                 - A[((c * 8 + i) * 10 + col) * 10 + m];
    }
    __syncthreads();

    int lane  = threadIdx.x & 31;
    int warpG = (blockIdx.x * blockDim.x + threadIdx.x) >> 5;
    int warpL = threadIdx.x >> 5;
    int g = lane / 5; if (g > 5) g = 5;      // lanes 30,31 shadow group 5
    int q = lane - g * 5; if (q > 4) q = 4;  // duplicate cols 8,9 (never stored)
    int unitRaw = warpG * 6 + g;
    int unit = (unitRaw < NU1) ? unitRaw : (NU1 - 1);
    bool active = (lane < 30) && (unitRaw < NU1);
    int chain = unit / SSEG;
    int seg   = unit % SSEG;
    int n = chain >> 1;
    int c = chain & 1;
    int j0 = q * 2;
    float* S = smat + warpL * WS + g * MS;
    const float* skb = skp + (c * 40 + q) * 20; // + i*100 per input dim

    const float4* X4 = (const float4*)x;
    int t0 = seg * LSEG;
    int rb = (n * T_T + t0) * 2;
    float4 xa = X4[rb], xb = X4[rb + 1];

    float P[2][10];
#pragma unroll
    for (int j = 0; j < 2; ++j)
#pragma unroll
        for (int r = 0; r < 10; ++r) P[j][r] = (r == j0 + j) ? 1.f : 0.f;

    const float a0 = 1.f, a1 = 1.f, a2 = 0.5f, a3 = 1.f/6.f,
                a4 = 1.f/24.f, a5 = 1.f/120.f, a6 = 1.f/720.f, a7 = 1.f/5040.f;

#pragma unroll 1
    for (int s = 0; s < LSEG; ++s) {
        int t = t0 + s;
        int tn = (t < NSTEP) ? (t + 1) : t; // tail: tn==t -> dx=0 -> E=I
        int rn = (n * T_T + tn) * 2;
        float4 ya = X4[rn], yb = X4[rn + 1];
        float dx[8];
        dx[0] = ya.x - xa.x; dx[1] = ya.y - xa.y; dx[2] = ya.z - xa.z; dx[3] = ya.w - xa.w;
        dx[4] = yb.x - xb.x; dx[5] = yb.y - xb.y; dx[6] = yb.z - xb.z; dx[7] = yb.w - xb.w;
        xa = ya; xb = yb;

        // G columns via vectorized skew reads
        float G[2][10];
#pragma unroll
        for (int j = 0; j < 2; ++j)
#pragma unroll
            for (int r = 0; r < 10; ++r) G[j][r] = 0.f;
#pragma unroll
        for (int i = 0; i < 8; ++i) {
            const float4* p = (const float4*)(skb + i * 100);
            float d = dx[i];
#pragma unroll
            for (int k = 0; k < 5; ++k) {
                float4 v = p[k];
                G[0][2*k]     = fmaf(d, v.x, G[0][2*k]);
                G[1][2*k]     = fmaf(d, v.y, G[1][2*k]);
                G[0][2*k + 1] = fmaf(d, v.z, G[0][2*k + 1]);
                G[1][2*k + 1] = fmaf(d, v.w, G[1][2*k + 1]);
            }
        }

        // S <- G ; acc = G@G ; S <- G2 (G2 never held in registers)
        __syncwarp();
        store_cols(S, G, j0);
        __syncwarp();
        float acc[2][10];
        mm10s(S, G, acc);
        __syncwarp();
        store_cols(S, acc, j0);
        __syncwarp();

        // W = B3 = a6*I + a7*G
        float W[2][10];
#pragma unroll
        for (int j = 0; j < 2; ++j)
#pragma unroll
            for (int r = 0; r < 10; ++r)
                W[j][r] = fmaf(a7, G[j][r], (r == j0 + j) ? a6 : 0.f);

        // Horner in G2 (left operand fixed in shared): W = G2@W + Bi, i=2,1,0
#pragma unroll
        for (int it = 2; it >= 0; --it) {
            float ai = (it == 2) ? a4 : (it == 1) ? a2 : a0;
            float bi = (it == 2) ? a5 : (it == 1) ? a3 : a1;
            mm10s(S, W, acc);
#pragma unroll
            for (int j = 0; j < 2; ++j)
#pragma unroll
                for (int r = 0; r < 10; ++r)
                    W[j][r] = fmaf(bi, G[j][r], acc[j][r]) + ((r == j0 + j) ? ai : 0.f);
        }

        // P <- P @ E
        __syncwarp();
        store_cols(S, P, j0);
        __syncwarp();
        mm10s(S, W, acc);
#pragma unroll
        for (int j = 0; j < 2; ++j)
#pragma unroll
            for (int r = 0; r < 10; ++r) P[j][r] = acc[j][r];
    }

    if (active) {
        float* dst = g_part1 + unit * 100 + j0 * 10;
#pragma unroll
        for (int j = 0; j < 2; ++j)
#pragma unroll
            for (int r = 0; r < 10; ++r) dst[j * 10 + r] = P[j][r];
    }
}

// Combine kernel: ordered product of GRP consecutive partials (smem matmul,
// next-E prefetch). mode 0: g_part1 -> g_part2 ; mode 1: g_part2 -> out.
__global__ void __launch_bounds__(256)
comb_kernel(int nUnits, int mode, float* __restrict__ out)
{
    __shared__ __align__(16) float smat[8 * WS];
    const float* src = (mode == 0) ? g_part1 : g_part2;
    int lane  = threadIdx.x & 31;
    int warpG = (blockIdx.x * blockDim.x + threadIdx.x) >> 5;
    int warpL = threadIdx.x >> 5;
    int g = lane / 5; if (g > 5) g = 5;
    int q = lane - g * 5; if (q > 4) q = 4;
    int unitRaw = warpG * 6 + g;
    int unit = (unitRaw < nUnits) ? unitRaw : (nUnits - 1);
    bool active = (lane < 30) && (unitRaw < nUnits);
    int j0 = q * 2;
    float* S = smat + warpL * WS + g * MS;

    const float* base = src + unit * (GRP * 100);
    float P[2][10];
#pragma unroll
    for (int j = 0; j < 2; ++j)
#pragma unroll
        for (int r = 0; r < 10; ++r)
            P[j][r] = base[(j0 + j) * 10 + r];

    float En[2][10];
#pragma unroll
    for (int j = 0; j < 2; ++j)
#pragma unroll
        for (int r = 0; r < 10; ++r)
            En[j][r] = base[100 + (j0 + j) * 10 + r];

#pragma unroll 1
    for (int e = 1; e < GRP; ++e) {
        float E[2][10];
#pragma unroll
        for (int j = 0; j < 2; ++j)
#pragma unroll
            for (int r = 0; r < 10; ++r) E[j][r] = En[j][r];
        if (e + 1 < GRP) {
            const float* nb = base + (e + 1) * 100;
#pragma unroll
            for (int j = 0; j < 2; ++j)
#pragma unroll
                for (int r = 0; r < 10; ++r)
                    En[j][r] = nb[(j0 + j) * 10 + r];
        }
        __syncwarp();
        store_cols(S, P, j0);
        __syncwarp();
        float acc[2][10];
        mm10s(S, E, acc);
#pragma unroll
        for (int j = 0; j < 2; ++j)
#pragma unroll
            for (int r = 0; r < 10; ++r) P[j][r] = acc[j][r];
    }

    if (active) {
        if (mode == 0) {
            float* dst = g_part2 + unit * 100 + j0 * 10;
#pragma unroll
            for (int j = 0; j < 2; ++j)
#pragma unroll
                for (int r = 0; r < 10; ++r) dst[j * 10 + r] = P[j][r];
        } else {
            float* dst = out + unit * 100; // unit == chain = n*C + c
#pragma unroll
            for (int j = 0; j < 2; ++j)
#pragma unroll
                for (int r = 0; r < 10; ++r) dst[r * 10 + (j0 + j)] = P[j][r];
        }
    }
}

extern "C" void kernel_launch(void* const* d_in, const int* in_sizes, int n_in,
                              void* d_out, int out_size)
{
    const float* x = (const float*)d_in[0];
    const float* A = (const float*)d_in[1];
    if (n_in >= 2 && in_sizes[0] == C_C * IN_P * M_M * M_M) { // defensive order check
        x = (const float*)d_in[1];
        A = (const float*)d_in[0];
    }
    float* out = (float*)d_out;

    int b1 = (NU1 + 47) / 48;
    seg_kernel<<<b1, 256>>>(x, A);
    int b2 = (NU2 + 47) / 48;
    comb_kernel<<<b2, 256>>>(NU2, 0, out);
    int b3 = (NU3 + 47) / 48;
    comb_kernel<<<b3, 256>>>(NU3, 1, out);
}

// round 9
// speedup vs baseline: 1.7880x; 1.0622x over previous
#include <cuda_runtime.h>

// Problem constants
#define N_B    64
#define T_T    2048
#define IN_P   8
#define C_C    2
#define M_M    10
#define NSTEP  2047            // number of increments (T-1)
#define LSEG   8               // steps per segment
#define SSEG   256             // segments per chain
#define NCHAIN 128             // N*C
#define NU1    (NCHAIN * SSEG) // 32768 segment units
#define GRP    16
#define NU2    (NCHAIN * (SSEG / GRP)) // 2048
#define NU3    NCHAIN                  // 128

#define CS 12                  // smem column stride (floats), 48B -> LDS.128-aligned
#define MS 132                 // smem matrix stride; 132 % 32 == 4 -> conflict-free across 6 groups
#define WS (6 * MS)            // per-warp tile stride (792 floats)
#define NWARP 4                // warps per block (128 threads)

// Scratch (static device arrays; allocation-free)
__device__ float g_part1[NU1 * 100]; // [unit][col][row], col-major per matrix
__device__ float g_part2[NU2 * 100];

// acc = S @ W : S is 10x10 col-major (stride CS) in shared; W = lane's 2 columns.
// 5 lanes of a group read the same address -> broadcast; groups land on
// disjoint bank quads (MS%32==4). 30 LDS insts per matmul.
__device__ __forceinline__ void mm10s(const float* __restrict__ S,
                                      const float W[2][10], float acc[2][10])
{
#pragma unroll
    for (int j = 0; j < 2; ++j)
#pragma unroll
        for (int r = 0; r < 10; ++r) acc[j][r] = 0.f;
#pragma unroll
    for (int m = 0; m < 10; ++m) {
        const float* col = S + m * CS;
        float4 v0 = *(const float4*)(col);
        float4 v1 = *(const float4*)(col + 4);
        float2 v2 = *(const float2*)(col + 8);
        float cv[10] = {v0.x, v0.y, v0.z, v0.w, v1.x, v1.y, v1.z, v1.w, v2.x, v2.y};
        float w0 = W[0][m], w1 = W[1][m];
#pragma unroll
        for (int r = 0; r < 10; ++r) acc[0][r] = fmaf(cv[r], w0, acc[0][r]);
#pragma unroll
        for (int r = 0; r < 10; ++r) acc[1][r] = fmaf(cv[r], w1, acc[1][r]);
    }
}

// Store lane's 2 columns into a broadcast tile (6 STS insts).
__device__ __forceinline__ void store_cols(float* __restrict__ S,
                                           const float V[2][10], int j0)
{
#pragma unroll
    for (int j = 0; j < 2; ++j) {
        float* p = S + (j0 + j) * CS;
        *(float4*)(p)     = make_float4(V[j][0], V[j][1], V[j][2], V[j][3]);
        *(float4*)(p + 4) = make_float4(V[j][4], V[j][5], V[j][6], V[j][7]);
        *(float2*)(p + 8) = make_float2(V[j][8], V[j][9]);
    }
}

// Kernel 1: per-(chain,segment) ordered product of expm(G_t), LSEG steps.
// exp(G): Paterson-Stockmeyer Horner-in-G^2, Taylor degree 7 (5 matmuls/step).
// P and G are evicted from the register file: P lives in broadcast tile Sp,
// G (elementwise uses only) lives in a conflict-free private SoA slot Gp.
__global__ void __launch_bounds__(128, 4)
seg_kernel(const float* __restrict__ x, const float* __restrict__ A)
{
    // skew repacked: skp[((c*8+i)*5+q)*20 + m*2 + jj] = skew[c][i][m][2q+jj]
    __shared__ __align__(16) float skp[1600];
    __shared__ __align__(16) float smat[NWARP * WS]; // G / G2 tile
    __shared__ __align__(16) float spt [NWARP * WS]; // P tile
    __shared__ __align__(16) float2 gp [NWARP * 10 * 32]; // private G SoA

    for (int idx = threadIdx.x; idx < 1600; idx += 128) {
        int jj = idx & 1;
        int m  = (idx >> 1) % 10;
        int qq = (idx / 20) % 5;
        int i  = (idx / 100) % 8;
        int c  = idx / 800;
        int col = 2 * qq + jj;
        skp[idx] = A[((c * 8 + i) * 10 + m) * 10 + col]
                 - A[((c * 8 + i) * 10 + col) * 10 + m];
    }
    __syncthreads();

    int lane  = threadIdx.x & 31;
    int warpG = (blockIdx.x * blockDim.x + threadIdx.x) >> 5;
    int warpL = threadIdx.x >> 5;
    int g = lane / 5; if (g > 5) g = 5;      // lanes 30,31 shadow group 5
    int q = lane - g * 5; if (q > 4) q = 4;  // duplicate cols 8,9 (benign)
    int unitRaw = warpG * 6 + g;
    int unit = (unitRaw < NU1) ? unitRaw : (NU1 - 1);
    bool active = (lane < 30) && (unitRaw < NU1);
    int chain = unit / SSEG;
    int seg   = unit % SSEG;
    int n = chain >> 1;
    int c = chain & 1;
    int j0 = q * 2;
    float*  S  = smat + warpL * WS + g * MS;
    float*  Sp = spt  + warpL * WS + g * MS;
    float2* Gl = gp + warpL * (10 * 32) + lane; // stride 32 per k
    const float* skb = skp + (c * 40 + q) * 20;

    const float4* X4 = (const float4*)x;
    int t0 = seg * LSEG;
    int rb = (n * T_T + t0) * 2;
    float4 xa = X4[rb], xb = X4[rb + 1];

    // P = I, stored straight to Sp
    {
        float Pi[2][10];
#pragma unroll
        for (int j = 0; j < 2; ++j)
#pragma unroll
            for (int r = 0; r < 10; ++r) Pi[j][r] = (r == j0 + j) ? 1.f : 0.f;
        store_cols(Sp, Pi, j0);
    }
    __syncwarp();

    const float a0 = 1.f, a1 = 1.f, a2 = 0.5f, a3 = 1.f/6.f,
                a4 = 1.f/24.f, a5 = 1.f/120.f, a6 = 1.f/720.f, a7 = 1.f/5040.f;

#pragma unroll 1
    for (int s = 0; s < LSEG; ++s) {
        int t = t0 + s;
        int tn = (t < NSTEP) ? (t + 1) : t; // tail: tn==t -> dx=0 -> E=I
        int rn = (n * T_T + tn) * 2;
        float4 ya = X4[rn], yb = X4[rn + 1];
        float dx[8];
        dx[0] = ya.x - xa.x; dx[1] = ya.y - xa.y; dx[2] = ya.z - xa.z; dx[3] = ya.w - xa.w;
        dx[4] = yb.x - xb.x; dx[5] = yb.y - xb.y; dx[6] = yb.z - xb.z; dx[7] = yb.w - xb.w;
        xa = ya; xb = yb;

        // G columns via vectorized skew reads
        float G[2][10];
#pragma unroll
        for (int j = 0; j < 2; ++j)
#pragma unroll
            for (int r = 0; r < 10; ++r) G[j][r] = 0.f;
#pragma unroll
        for (int i = 0; i < 8; ++i) {
            const float4* p = (const float4*)(skb + i * 100);
            float d = dx[i];
#pragma unroll
            for (int k = 0; k < 5; ++k) {
                float4 v = p[k];
                G[0][2*k]     = fmaf(d, v.x, G[0][2*k]);
                G[1][2*k]     = fmaf(d, v.y, G[1][2*k]);
                G[0][2*k + 1] = fmaf(d, v.z, G[0][2*k + 1]);
                G[1][2*k + 1] = fmaf(d, v.w, G[1][2*k + 1]);
            }
        }

        // Park G: broadcast tile (matmul left-op) + private SoA (elementwise)
        store_cols(S, G, j0);
#pragma unroll
        for (int j = 0; j < 2; ++j)
#pragma unroll
            for (int rr = 0; rr < 5; ++rr)
                Gl[(j * 5 + rr) * 32] = make_float2(G[j][2*rr], G[j][2*rr + 1]);
        __syncwarp();

        // G2 = G @ G (G register copy dies here)
        float acc[2][10];
        mm10s(S, G, acc);
        __syncwarp();
        store_cols(S, acc, j0);   // S <- G2
        __syncwarp();

        // W = B3 = a6*I + a7*G   (G from private smem)
        float W[2][10];
#pragma unroll
        for (int j = 0; j < 2; ++j)
#pragma unroll
            for (int rr = 0; rr < 5; ++rr) {
                float2 gv = Gl[(j * 5 + rr) * 32];
                W[j][2*rr]     = fmaf(a7, gv.x, (2*rr     == j0 + j) ? a6 : 0.f);
                W[j][2*rr + 1] = fmaf(a7, gv.y, (2*rr + 1 == j0 + j) ? a6 : 0.f);
            }

        // Horner in G2: W = G2@W + Bi, i = 2,1,0
#pragma unroll
        for (int it = 2; it >= 0; --it) {
            float ai = (it == 2) ? a4 : (it == 1) ? a2 : a0;
            float bi = (it == 2) ? a5 : (it == 1) ? a3 : a1;
            mm10s(S, W, acc);
#pragma unroll
            for (int j = 0; j < 2; ++j)
#pragma unroll
                for (int rr = 0; rr < 5; ++rr) {
                    float2 gv = Gl[(j * 5 + rr) * 32];
                    W[j][2*rr]     = fmaf(bi, gv.x, acc[j][2*rr])
                                   + ((2*rr     == j0 + j) ? ai : 0.f);
                    W[j][2*rr + 1] = fmaf(bi, gv.y, acc[j][2*rr + 1])
                                   + ((2*rr + 1 == j0 + j) ? ai : 0.f);
                }
        }

        // P <- P @ E  (P read from Sp, new P written back to Sp)
        mm10s(Sp, W, acc);
        __syncwarp();
        store_cols(Sp, acc, j0);
        __syncwarp();
    }

    if (active) {
        float* dst = g_part1 + unit * 100 + j0 * 10;
#pragma unroll
        for (int j = 0; j < 2; ++j) {
            const float* p = Sp + (j0 + j) * CS;
#pragma unroll
            for (int r = 0; r < 10; ++r) dst[j * 10 + r] = p[r];
        }
    }
}

// Combine kernel: ordered product of GRP consecutive partials (smem matmul,
// next-E prefetch). mode 0: g_part1 -> g_part2 ; mode 1: g_part2 -> out.
__global__ void __launch_bounds__(128, 4)
comb_kernel(int nUnits, int mode, float* __restrict__ out)
{
    __shared__ __align__(16) float smat[NWARP * WS];
    const float* src = (mode == 0) ? g_part1 : g_part2;
    int lane  = threadIdx.x & 31;
    int warpG = (blockIdx.x * blockDim.x + threadIdx.x) >> 5;
    int warpL = threadIdx.x >> 5;
    int g = lane / 5; if (g > 5) g = 5;
    int q = lane - g * 5; if (q > 4) q = 4;
    int unitRaw = warpG * 6 + g;
    int unit = (unitRaw < nUnits) ? unitRaw : (nUnits - 1);
    bool active = (lane < 30) && (unitRaw < nUnits);
    int j0 = q * 2;
    float* S = smat + warpL * WS + g * MS;

    const float* base = src + unit * (GRP * 100);
    float P[2][10];
#pragma unroll
    for (int j = 0; j < 2; ++j)
#pragma unroll
        for (int r = 0; r < 10; ++r)
            P[j][r] = base[(j0 + j) * 10 + r];

    float En[2][10];
#pragma unroll
    for (int j = 0; j < 2; ++j)
#pragma unroll
        for (int r = 0; r < 10; ++r)
            En[j][r] = base[100 + (j0 + j) * 10 + r];

#pragma unroll 1
    for (int e = 1; e < GRP; ++e) {
        float E[2][10];
#pragma unroll
        for (int j = 0; j < 2; ++j)
#pragma unroll
            for (int r = 0; r < 10; ++r) E[j][r] = En[j][r];
        if (e + 1 < GRP) {
            const float* nb = base + (e + 1) * 100;
#pragma unroll
            for (int j = 0; j < 2; ++j)
#pragma unroll
                for (int r = 0; r < 10; ++r)
                    En[j][r] = nb[(j0 + j) * 10 + r];
        }
        __syncwarp();
        store_cols(S, P, j0);
        __syncwarp();
        float acc[2][10];
        mm10s(S, E, acc);
#pragma unroll
        for (int j = 0; j < 2; ++j)
#pragma unroll
            for (int r = 0; r < 10; ++r) P[j][r] = acc[j][r];
    }

    if (active) {
        if (mode == 0) {
            float* dst = g_part2 + unit * 100 + j0 * 10;
#pragma unroll
            for (int j = 0; j < 2; ++j)
#pragma unroll
                for (int r = 0; r < 10; ++r) dst[j * 10 + r] = P[j][r];
        } else {
            float* dst = out + unit * 100; // unit == chain = n*C + c
#pragma unroll
            for (int j = 0; j < 2; ++j)
#pragma unroll
                for (int r = 0; r < 10; ++r) dst[r * 10 + (j0 + j)] = P[j][r];
        }
    }
}

extern "C" void kernel_launch(void* const* d_in, const int* in_sizes, int n_in,
                              void* d_out, int out_size)
{
    const float* x = (const float*)d_in[0];
    const float* A = (const float*)d_in[1];
    if (n_in >= 2 && in_sizes[0] == C_C * IN_P * M_M * M_M) { // defensive order check
        x = (const float*)d_in[1];
        A = (const float*)d_in[0];
    }
    float* out = (float*)d_out;

    // 128 threads = 4 warps = 24 units per block
    int b1 = (NU1 + 23) / 24;
    seg_kernel<<<b1, 128>>>(x, A);
    int b2 = (NU2 + 23) / 24;
    comb_kernel<<<b2, 128>>>(NU2, 0, out);
    int b3 = (NU3 + 23) / 24;
    comb_kernel<<<b3, 128>>>(NU3, 1, out);
}